// round 3
// baseline (speedup 1.0000x reference)
#include <cuda_runtime.h>

static constexpr int C = 1000;
static constexpr int D = 128;
static constexpr int NMAX = 1000000;

// Scratch (device globals — no allocation allowed in kernel_launch)
__device__ int   g_counts[C];
__device__ int   g_offsets[C];
__device__ int   g_cursor[C];
__device__ int   g_idx[NMAX];
__device__ float g_means[C * D];
__device__ int   g_flag32;   // nonzero => labels are int32 (odd words nonzero)

// Read label i, handling both int32 and int64 (little-endian) storage.
__device__ __forceinline__ int load_label(const int* __restrict__ lab32, int i, int is64) {
    return is64 ? lab32[2 * i] : lab32[i];
}

// ---------------------------------------------------------------------------
// K0: zero flags + histogram (must re-run every graph replay)
// ---------------------------------------------------------------------------
__global__ void k_zero() {
    int t = blockIdx.x * blockDim.x + threadIdx.x;
    if (t < C) g_counts[t] = 0;
    if (t == 0) g_flag32 = 0;
}

// ---------------------------------------------------------------------------
// K0b: dtype detect — if any odd 32-bit word is nonzero, labels are int32.
// ---------------------------------------------------------------------------
__global__ void __launch_bounds__(256) k_detect(const int* __restrict__ lab32, int n) {
    int stride = gridDim.x * blockDim.x;
    int found = 0;
    for (int i = blockIdx.x * blockDim.x + threadIdx.x; i < n / 2; i += stride)
        found |= (lab32[2 * i + 1] != 0);
    if (__syncthreads_or(found) && threadIdx.x == 0)
        atomicOr(&g_flag32, 1);
}

// ---------------------------------------------------------------------------
// K1: smem-privatized label histogram
// ---------------------------------------------------------------------------
__global__ void __launch_bounds__(256) k_hist(const int* __restrict__ lab32, int n) {
    __shared__ int sh[C];
    int is64 = (g_flag32 == 0);
    for (int i = threadIdx.x; i < C; i += blockDim.x) sh[i] = 0;
    __syncthreads();
    int stride = gridDim.x * blockDim.x;
    for (int i = blockIdx.x * blockDim.x + threadIdx.x; i < n; i += stride) {
        int c = load_label(lab32, i, is64);
        if ((unsigned)c < (unsigned)C) atomicAdd(&sh[c], 1);
    }
    __syncthreads();
    for (int i = threadIdx.x; i < C; i += blockDim.x) {
        int v = sh[i];
        if (v) atomicAdd(&g_counts[i], v);
    }
}

// ---------------------------------------------------------------------------
// K2: single-CTA exclusive scan of counts -> offsets + scatter cursors
// ---------------------------------------------------------------------------
__global__ void __launch_bounds__(1024) k_scan() {
    __shared__ int sh[1024];
    int t = threadIdx.x;
    int v = (t < C) ? g_counts[t] : 0;
    sh[t] = v;
    __syncthreads();
    for (int off = 1; off < 1024; off <<= 1) {
        int x = (t >= off) ? sh[t - off] : 0;
        __syncthreads();
        sh[t] += x;
        __syncthreads();
    }
    if (t < C) {
        int ex = sh[t] - v;      // exclusive prefix
        g_offsets[t] = ex;
        g_cursor[t]  = ex;
    }
}

// ---------------------------------------------------------------------------
// K3: scatter row indices into class-sorted order
// ---------------------------------------------------------------------------
__global__ void __launch_bounds__(256) k_scatter(const int* __restrict__ lab32, int n) {
    int is64 = (g_flag32 == 0);
    int stride = gridDim.x * blockDim.x;
    for (int i = blockIdx.x * blockDim.x + threadIdx.x; i < n; i += stride) {
        int c = load_label(lab32, i, is64);
        if ((unsigned)c >= (unsigned)C) continue;
        int p = atomicAdd(&g_cursor[c], 1);
        g_idx[p] = i;
    }
}

// ---------------------------------------------------------------------------
// K4: per-class sum via register accumulation (one CTA per class)
//     warp = one 512B row (32 x float4), 8 rows in flight, unroll x4 for MLP
// ---------------------------------------------------------------------------
__global__ void __launch_bounds__(256) k_class_sum(const float* __restrict__ emb) {
    int c = blockIdx.x;
    int start = g_offsets[c];
    int cnt = g_counts[c];
    int lane = threadIdx.x & 31;   // float4 slot within row
    int grp  = threadIdx.x >> 5;   // 0..7, row group

    const float4* __restrict__ e4 = (const float4*)emb;
    float4 a = make_float4(0.f, 0.f, 0.f, 0.f);

    int r = grp;
    for (; r + 24 < cnt; r += 32) {
        int i0 = g_idx[start + r];
        int i1 = g_idx[start + r + 8];
        int i2 = g_idx[start + r + 16];
        int i3 = g_idx[start + r + 24];
        float4 v0 = e4[(size_t)i0 * 32 + lane];
        float4 v1 = e4[(size_t)i1 * 32 + lane];
        float4 v2 = e4[(size_t)i2 * 32 + lane];
        float4 v3 = e4[(size_t)i3 * 32 + lane];
        a.x += (v0.x + v1.x) + (v2.x + v3.x);
        a.y += (v0.y + v1.y) + (v2.y + v3.y);
        a.z += (v0.z + v1.z) + (v2.z + v3.z);
        a.w += (v0.w + v1.w) + (v2.w + v3.w);
    }
    for (; r < cnt; r += 8) {
        int i0 = g_idx[start + r];
        float4 v = e4[(size_t)i0 * 32 + lane];
        a.x += v.x; a.y += v.y; a.z += v.z; a.w += v.w;
    }

    __shared__ float4 sh[8][32];
    sh[grp][lane] = a;
    __syncthreads();
    if (grp == 0) {
        float4 s = sh[0][lane];
#pragma unroll
        for (int g = 1; g < 8; g++) {
            float4 v = sh[g][lane];
            s.x += v.x; s.y += v.y; s.z += v.z; s.w += v.w;
        }
        float inv = (cnt > 0) ? (1.0f / (float)cnt) : 0.f;
        float4 m = make_float4(s.x * inv, s.y * inv, s.z * inv, s.w * inv);
        ((float4*)g_means)[c * 32 + lane] = m;
    }
}

// ---------------------------------------------------------------------------
// K5: variance of class means (ddof=1) per dim, mean over dims, negate
// ---------------------------------------------------------------------------
__global__ void __launch_bounds__(1024) k_finalize(float* __restrict__ out) {
    __shared__ float sh[8][128];
    __shared__ float shmean[128];
    int t = threadIdx.x;
    int d  = t & 127;   // dim
    int ch = t >> 7;    // class chunk 0..7

    // pass 1: per-dim mean over classes
    float s = 0.f;
    for (int c = ch; c < C; c += 8)
        s += g_means[c * D + d];
    sh[ch][d] = s;
    __syncthreads();
    if (ch == 0) {
        float m = 0.f;
#pragma unroll
        for (int g = 0; g < 8; g++) m += sh[g][d];
        shmean[d] = m / (float)C;
    }
    __syncthreads();

    // pass 2: per-dim unbiased variance
    float mean = shmean[d];
    float sq = 0.f;
    for (int c = ch; c < C; c += 8) {
        float x = g_means[c * D + d] - mean;
        sq += x * x;
    }
    __syncthreads();   // all reads of shmean done before reuse
    sh[ch][d] = sq;
    __syncthreads();
    if (t < 128) {
        float v = 0.f;
#pragma unroll
        for (int g = 0; g < 8; g++) v += sh[g][t];
        shmean[t] = v / (float)(C - 1);
    }
    __syncthreads();
    if (t == 0) {
        float acc = 0.f;
        for (int dd = 0; dd < 128; dd++) acc += shmean[dd];
        out[0] = -(acc / (float)D);
    }
}

// ---------------------------------------------------------------------------
extern "C" void kernel_launch(void* const* d_in, const int* in_sizes, int n_in,
                              void* d_out, int out_size) {
    // embeddings = the big fp32 buffer (128M elems), labels = the 1M-elem buffer
    const float* emb;
    const int*   lab32;   // raw 32-bit view of labels; dtype resolved on device
    int n;
    if (in_sizes[0] > in_sizes[1]) {
        emb   = (const float*)d_in[0];
        lab32 = (const int*)d_in[1];
        n     = in_sizes[1];
    } else {
        emb   = (const float*)d_in[1];
        lab32 = (const int*)d_in[0];
        n     = in_sizes[0];
    }
    float* out = (float*)d_out;

    k_zero<<<1, 1024>>>();
    k_detect<<<128, 256>>>(lab32, n);
    k_hist<<<296, 256>>>(lab32, n);
    k_scan<<<1, 1024>>>();
    k_scatter<<<296, 256>>>(lab32, n);
    k_class_sum<<<C, 256>>>(emb);
    k_finalize<<<1, 1024>>>(out);
}